// round 15
// baseline (speedup 1.0000x reference)
#include <cuda_runtime.h>
#include <cuda_fp16.h>
#include <cstdint>
#include <cstddef>

#define BATCH 1024
#define HW 1024   // 32*32

// ---------------- scratch (device globals; no allocs allowed) ----------------
__device__ __half g_H[(size_t)BATCH * HW * 64];   // fp16 NHWC activations
__device__ __half g_R[(size_t)BATCH * HW * 64];
__device__ __half g_U[4 * 16 * 64 * 72];          // winograd weights [layer][pos][co][ci pad 72]
__device__ __half g_W0[64 * 40];                  // conv0 im2col weights
__device__ float g_gap[BATCH * 64];
__device__ int   g_flag[BATCH];

// ---------------- misc ----------------
__global__ void zero_conf(float* conf) {
    int t = threadIdx.x;
    if (t < 100) conf[t] = 0.0f;
}

// winograd weight prep: per layer, OIHW fp32 -> U = G g G^T, [pos16][co64][ci pad72] fp16
__global__ void prep_wu(const float* w1a, const float* w1b, const float* w2a,
                        const float* w2b, __half* __restrict__ u) {
    int idx = blockIdx.x * 256 + threadIdx.x;   // (co,ci) pair, 4096 per layer
    if (idx >= 4096) return;
    int layer = blockIdx.y;
    const float* w = (layer == 0) ? w1a : (layer == 1) ? w1b : (layer == 2) ? w2a : w2b;
    int co = idx >> 6, ci = idx & 63;
    float gm[3][3];
    #pragma unroll
    for (int r = 0; r < 3; r++)
        #pragma unroll
        for (int c = 0; c < 3; c++) gm[r][c] = w[(co * 64 + ci) * 9 + r * 3 + c];
    float T[4][3];
    #pragma unroll
    for (int c = 0; c < 3; c++) {
        T[0][c] = gm[0][c];
        T[1][c] = 0.5f * (gm[0][c] + gm[1][c] + gm[2][c]);
        T[2][c] = 0.5f * (gm[0][c] - gm[1][c] + gm[2][c]);
        T[3][c] = gm[2][c];
    }
    __half* ub = u + (size_t)layer * 16 * 64 * 72;
    #pragma unroll
    for (int r = 0; r < 4; r++) {
        float u0 = T[r][0];
        float u1 = 0.5f * (T[r][0] + T[r][1] + T[r][2]);
        float u2 = 0.5f * (T[r][0] - T[r][1] + T[r][2]);
        float u3 = T[r][2];
        ub[(r * 4 + 0) * 4608 + co * 72 + ci] = __float2half(u0);
        ub[(r * 4 + 1) * 4608 + co * 72 + ci] = __float2half(u1);
        ub[(r * 4 + 2) * 4608 + co * 72 + ci] = __float2half(u2);
        ub[(r * 4 + 3) * 4608 + co * 72 + ci] = __float2half(u3);
    }
}

// conv0 weight prep: [64][3][3][3] fp32 -> [co][k pad 40] fp16
__global__ void prep_w0(const float* __restrict__ w, __half* __restrict__ wo) {
    int idx = blockIdx.x * 256 + threadIdx.x;
    if (idx >= 64 * 40) return;
    int co = idx / 40, k = idx % 40;
    float v = (k < 27) ? w[co * 27 + k] : 0.0f;
    wo[idx] = __float2half(v);
}

// ---------------- fused LeNet (fp32 exact) + gap zeroing ----------------
__global__ __launch_bounds__(256) void lenet_all(
        const float* __restrict__ x, const float* __restrict__ w1, const float* __restrict__ b1,
        const float* __restrict__ w2, const float* __restrict__ b2,
        const float* __restrict__ fc1w, const float* __restrict__ fc1b,
        const float* __restrict__ fc2w, const float* __restrict__ fc2b,
        const float* __restrict__ fc3w, const float* __restrict__ fc3b,
        const float* __restrict__ thr_p, const int* __restrict__ labels,
        float* __restrict__ lenout, float* conf, int* __restrict__ flag,
        float* __restrict__ gapz) {
    __shared__ float sx[3 * 32 * 32];
    __shared__ float sw[2400];
    __shared__ float p1[1176];
    __shared__ float p2[400];
    __shared__ float h1[120];
    __shared__ float h2[84];
    __shared__ float lg[10];
    __shared__ float sb[16];
    int bid = blockIdx.x, t = threadIdx.x;
    if (t < 64) gapz[bid * 64 + t] = 0.0f;
    const float* xb = x + (size_t)bid * 3072;
    for (int i = t; i < 3072; i += 256) sx[i] = xb[i];
    for (int i = t; i < 450; i += 256) sw[i] = w1[i];
    if (t < 6) sb[t] = b1[t];
    __syncthreads();
    for (int idx = t; idx < 6 * 14 * 14; idx += 256) {
        int c = idx / 196, py = (idx / 14) % 14, px = idx % 14;
        float m = -1e30f;
        #pragma unroll
        for (int dy = 0; dy < 2; dy++)
            #pragma unroll
            for (int dx = 0; dx < 2; dx++) {
                int y = 2 * py + dy, x0 = 2 * px + dx;
                float a = sb[c];
                for (int ci = 0; ci < 3; ci++)
                    #pragma unroll
                    for (int ky = 0; ky < 5; ky++)
                        #pragma unroll
                        for (int kx = 0; kx < 5; kx++)
                            a = fmaf(sx[ci * 1024 + (y + ky) * 32 + (x0 + kx)],
                                     sw[(c * 3 + ci) * 25 + ky * 5 + kx], a);
                m = fmaxf(m, a);
            }
        p1[idx] = fmaxf(m, 0.0f);
    }
    __syncthreads();
    for (int i = t; i < 2400; i += 256) sw[i] = w2[i];
    if (t < 16) sb[t] = b2[t];
    __syncthreads();
    for (int idx = t; idx < 400; idx += 256) {
        int c = idx / 25, py = (idx / 5) % 5, px = idx % 5;
        float m = -1e30f;
        #pragma unroll
        for (int dy = 0; dy < 2; dy++)
            #pragma unroll
            for (int dx = 0; dx < 2; dx++) {
                int y = 2 * py + dy, x0 = 2 * px + dx;
                float a = sb[c];
                for (int ci = 0; ci < 6; ci++)
                    #pragma unroll
                    for (int ky = 0; ky < 5; ky++)
                        #pragma unroll
                        for (int kx = 0; kx < 5; kx++)
                            a = fmaf(p1[ci * 196 + (y + ky) * 14 + (x0 + kx)],
                                     sw[(c * 6 + ci) * 25 + ky * 5 + kx], a);
                m = fmaxf(m, a);
            }
        p2[idx] = fmaxf(m, 0.0f);
    }
    __syncthreads();
    if (t < 120) {
        float a = fc1b[t];
        for (int k = 0; k < 400; k++) a = fmaf(p2[k], fc1w[k * 120 + t], a);
        h1[t] = fmaxf(a, 0.0f);
    }
    __syncthreads();
    if (t < 84) {
        float a = fc2b[t];
        for (int k = 0; k < 120; k++) a = fmaf(h1[k], fc2w[k * 84 + t], a);
        h2[t] = fmaxf(a, 0.0f);
    }
    __syncthreads();
    if (t < 10) {
        float a = fc3b[t];
        for (int k = 0; k < 84; k++) a = fmaf(h2[k], fc3w[k * 10 + t], a);
        lg[t] = a;
        lenout[(size_t)bid * 10 + t] = a;
    }
    __syncthreads();
    if (t == 0) {
        float m = lg[0]; int am = 0;
        #pragma unroll
        for (int i = 1; i < 10; i++) if (lg[i] > m) { m = lg[i]; am = i; }
        float p[10]; float s = 0.0f;
        #pragma unroll
        for (int i = 0; i < 10; i++) { p[i] = expf(lg[i] - m); s += p[i]; }
        float inv = 1.0f / s;
        float p0 = -1.0f, pp1 = -1.0f;
        #pragma unroll
        for (int i = 0; i < 10; i++) {
            float v = p[i] * inv;
            if (v > p0) { pp1 = p0; p0 = v; } else if (v > pp1) { pp1 = v; }
        }
        flag[bid] = ((p0 - pp1) <= thr_p[0]) ? 1 : 0;
        atomicAdd(&conf[labels[bid] * 10 + am], 1.0f);
    }
}

// ---------------- mma/ldmatrix helpers ----------------
__device__ __forceinline__ void mma_f16(float* d, uint32_t a0, uint32_t a1, uint32_t a2,
                                        uint32_t a3, uint32_t b0, uint32_t b1) {
    asm volatile("mma.sync.aligned.m16n8k16.row.col.f32.f16.f16.f32 "
                 "{%0,%1,%2,%3}, {%4,%5,%6,%7}, {%8,%9}, {%0,%1,%2,%3};"
                 : "+f"(d[0]), "+f"(d[1]), "+f"(d[2]), "+f"(d[3])
                 : "r"(a0), "r"(a1), "r"(a2), "r"(a3), "r"(b0), "r"(b1));
}
__device__ __forceinline__ void ldsm4(uint32_t& r0, uint32_t& r1, uint32_t& r2, uint32_t& r3,
                                      uint32_t addr) {
    asm volatile("ldmatrix.sync.aligned.m8n8.x4.shared.b16 {%0,%1,%2,%3}, [%4];"
                 : "=r"(r0), "=r"(r1), "=r"(r2), "=r"(r3) : "r"(addr));
}
__device__ __forceinline__ void ldsm2(uint32_t& r0, uint32_t& r1, uint32_t addr) {
    asm volatile("ldmatrix.sync.aligned.m8n8.x2.shared.b16 {%0,%1}, [%2];"
                 : "=r"(r0), "=r"(r1) : "r"(addr));
}

// ---------------- conv0 as im2col fp16 GEMM ----------------
#define C0_SIN 0
#define C0_A   1080
#define C0_B   2360
#define C0_SMEM_BYTES (256 * 68 * 4)

__global__ __launch_bounds__(256, 2) void conv0_mma(const float* __restrict__ x,
        const __half* __restrict__ w0, const float* __restrict__ bias,
        __half* __restrict__ out) {
    extern __shared__ uint32_t sm[];
    uint32_t sbase = (uint32_t)__cvta_generic_to_shared(sm);
    float* sin = reinterpret_cast<float*>(sm + C0_SIN);
    int b = blockIdx.x, row0 = blockIdx.y * 8;
    int t = threadIdx.x, lane = t & 31, warp = t >> 5;
    int cobase = (warp >> 2) * 32;
    int pxbase = (warp & 3) * 64;

    const float* inb = x + (size_t)b * 3 * HW;
    for (int idx = t; idx < 3 * 340; idx += 256) {
        int kc = idx / 340, rem = idx % 340, r = rem / 34, c = rem % 34;
        int gr = row0 - 1 + r, gc = c - 1;
        float v = 0.0f;
        if ((unsigned)gr < 32u && (unsigned)gc < 32u)
            v = inb[(size_t)kc * HW + gr * 32 + gc];
        sin[kc * 360 + r * 36 + c] = v;
    }
    for (int i = t; i < 1280; i += 256)
        sm[C0_A + i] = reinterpret_cast<const uint32_t*>(w0)[i];
    __syncthreads();
    {
        int r = t >> 5, c = t & 31;
        __half hv[32];
        #pragma unroll
        for (int ci = 0; ci < 3; ci++)
            #pragma unroll
            for (int ky = 0; ky < 3; ky++)
                #pragma unroll
                for (int kx = 0; kx < 3; kx++)
                    hv[ci * 9 + ky * 3 + kx] =
                        __float2half(sin[ci * 360 + (r + ky) * 36 + (c + kx)]);
        #pragma unroll
        for (int k = 27; k < 32; k++) hv[k] = __float2half(0.0f);
        uint32_t* hw = reinterpret_cast<uint32_t*>(hv);
        #pragma unroll
        for (int wv = 0; wv < 16; wv++) sm[C0_B + t * 20 + wv] = hw[wv];
    }
    __syncthreads();

    float acc[2][8][4];
    #pragma unroll
    for (int mt = 0; mt < 2; mt++) {
        float bv0 = bias[cobase + mt * 16 + (lane >> 2)];
        float bv1 = bias[cobase + mt * 16 + (lane >> 2) + 8];
        #pragma unroll
        for (int j = 0; j < 8; j++) {
            acc[mt][j][0] = bv0; acc[mt][j][1] = bv0;
            acc[mt][j][2] = bv1; acc[mt][j][3] = bv1;
        }
    }
    int a_mhalf = (lane >> 3) & 1, a_khalf = lane >> 4, a_row = lane & 7;
    int b_pxg = lane >> 4, b_khalf = (lane >> 3) & 1, b_row = lane & 7;
    #pragma unroll
    for (int q = 0; q < 2; q++) {
        uint32_t ah[2][4];
        #pragma unroll
        for (int mt = 0; mt < 2; mt++) {
            int aoff = (cobase + mt * 16 + a_mhalf * 8 + a_row) * 20 + q * 8 + a_khalf * 4;
            ldsm4(ah[mt][0], ah[mt][1], ah[mt][2], ah[mt][3], sbase + (C0_A + aoff) * 4);
        }
        #pragma unroll
        for (int jp = 0; jp < 4; jp++) {
            uint32_t bh[4];
            int p = pxbase + jp * 16 + b_pxg * 8 + b_row;
            int boff = p * 20 + q * 8 + b_khalf * 4;
            ldsm4(bh[0], bh[1], bh[2], bh[3], sbase + (C0_B + boff) * 4);
            #pragma unroll
            for (int sub = 0; sub < 2; sub++) {
                int j = jp * 2 + sub, hf = sub * 2;
                #pragma unroll
                for (int mt = 0; mt < 2; mt++)
                    mma_f16(acc[mt][j], ah[mt][0], ah[mt][1], ah[mt][2], ah[mt][3],
                            bh[hf], bh[hf + 1]);
            }
        }
    }
    float* smf = reinterpret_cast<float*>(sm);
    __syncthreads();
    #pragma unroll
    for (int mt = 0; mt < 2; mt++) {
        int col = cobase + mt * 16 + (lane >> 2);
        #pragma unroll
        for (int j = 0; j < 8; j++) {
            int p0 = pxbase + j * 8 + (lane & 3) * 2;
            smf[p0 * 68 + col]            = acc[mt][j][0];
            smf[(p0 + 1) * 68 + col]      = acc[mt][j][1];
            smf[p0 * 68 + col + 8]        = acc[mt][j][2];
            smf[(p0 + 1) * 68 + col + 8]  = acc[mt][j][3];
        }
    }
    __syncthreads();
    size_t obase = ((size_t)b * HW + row0 * 32) * 64;
    for (int idx = t; idx < 4096; idx += 256) {
        int px = idx >> 4, ck = idx & 15;
        float4 v = *reinterpret_cast<const float4*>(smf + px * 68 + ck * 4);
        v.x = fmaxf(v.x, 0.f); v.y = fmaxf(v.y, 0.f);
        v.z = fmaxf(v.z, 0.f); v.w = fmaxf(v.w, 0.f);
        __half h[4];
        h[0] = __float2half(v.x); h[1] = __float2half(v.y);
        h[2] = __float2half(v.z); h[3] = __float2half(v.w);
        *reinterpret_cast<uint2*>(out + obase + (size_t)px * 64 + ck * 4) =
            *reinterpret_cast<uint2*>(h);
    }
}

// ---------------- Winograd F(2x2,3x3) conv 64->64, fp16 tensor-core ----------------
// CTA: 1 tile-row (2 output rows x 32 cols = 16 tiles), grid (BATCH, 16).
// smem words: IN 4x34 px x 36w = 4896; V 16 pos x 16 tiles x 36w = 9216; U 2 x 2304
#define WG_IN   0
#define WG_V    4896
#define WG_U    14112
#define WG_WORDS 18720
#define WG_BYTES (WG_WORDS * 4)    // 74880 -> 3 CTAs/SM

__global__ __launch_bounds__(256, 3) void conv_wino(
        const __half* __restrict__ in, const __half* __restrict__ u,
        const float* __restrict__ bias, const __half* res,
        __half* __restrict__ out, float* gap) {
    extern __shared__ uint32_t sm[];
    uint32_t sbase = (uint32_t)__cvta_generic_to_shared(sm);
    int b = blockIdx.x, g = blockIdx.y;          // output rows 2g, 2g+1
    int t = threadIdx.x, lane = t & 31, warp = t >> 5;
    int mq = warp >> 1, nq = warp & 1;           // co tile m16, tile-group n8

    // ---- stage input: rows 2g-1..2g+2, cols -1..32 (4x34 px), [px][ci] pitch 36w ----
    const __half* ibase = in + (size_t)b * HW * 64;
    for (int idx = t; idx < 1088; idx += 256) {  // 136 px * 8 chunks
        int pxt = idx >> 3, ck = idx & 7;
        int rt = pxt / 34, ct = pxt % 34;
        int gr = 2 * g - 1 + rt, gc = ct - 1;
        int ok = ((unsigned)gr < 32u) && ((unsigned)gc < 32u);
        const char* src = reinterpret_cast<const char*>(
            ibase + (ok ? ((size_t)(gr * 32 + gc)) * 64 + ck * 8 : 0));
        uint32_t dst = (uint32_t)__cvta_generic_to_shared(sm + WG_IN + pxt * 36 + ck * 4);
        int sz = ok ? 16 : 0;
        asm volatile("cp.async.ca.shared.global [%0], [%1], 16, %2;"
                     :: "r"(dst), "l"(src), "r"(sz));
    }
    auto issueU = [&](int pos, int buf) {
        for (int c = t; c < 576; c += 256) {     // 9216 B per pos
            const char* src = reinterpret_cast<const char*>(u) + (size_t)pos * 9216 + c * 16;
            uint32_t dst = (uint32_t)__cvta_generic_to_shared(
                sm + WG_U + buf * 2304 + c * 4);
            asm volatile("cp.async.ca.shared.global [%0], [%1], 16;" :: "r"(dst), "l"(src));
        }
        asm volatile("cp.async.commit_group;" ::: "memory");
    };
    issueU(0, 0);                                 // commits input + U0 together

    asm volatile("cp.async.wait_group 0;" ::: "memory");
    __syncthreads();

    // ---- input transform: V = B^T d B per (tile, ci); 4 units/thread ----
    {
        const __half* sIN = reinterpret_cast<const __half*>(sm + WG_IN);
        __half* sV = reinterpret_cast<__half*>(sm + WG_V);
        #pragma unroll
        for (int k = 0; k < 4; k++) {
            int unit = t + k * 256;              // 16 tiles * 64 ci
            int tile = unit >> 6, ci = unit & 63;
            float d[4][4];
            #pragma unroll
            for (int r = 0; r < 4; r++)
                #pragma unroll
                for (int c = 0; c < 4; c++)
                    d[r][c] = __half2float(sIN[(r * 34 + tile * 2 + c) * 72 + ci]);
            float tm[4][4];
            #pragma unroll
            for (int c = 0; c < 4; c++) {
                tm[0][c] = d[0][c] - d[2][c];
                tm[1][c] = d[1][c] + d[2][c];
                tm[2][c] = d[2][c] - d[1][c];
                tm[3][c] = d[1][c] - d[3][c];
            }
            #pragma unroll
            for (int r = 0; r < 4; r++) {
                float v0 = tm[r][0] - tm[r][2];
                float v1 = tm[r][1] + tm[r][2];
                float v2 = tm[r][2] - tm[r][1];
                float v3 = tm[r][1] - tm[r][3];
                sV[(r * 4 + 0) * 1152 + tile * 72 + ci] = __float2half(v0);
                sV[(r * 4 + 1) * 1152 + tile * 72 + ci] = __float2half(v1);
                sV[(r * 4 + 2) * 1152 + tile * 72 + ci] = __float2half(v2);
                sV[(r * 4 + 3) * 1152 + tile * 72 + ci] = __float2half(v3);
            }
        }
    }
    __syncthreads();

    // ---- 16 position GEMMs, inverse transform fused into register accumulation ----
    float Y[4][4];                                // [acc slot][x*2+y]
    #pragma unroll
    for (int v = 0; v < 4; v++)
        #pragma unroll
        for (int p = 0; p < 4; p++) Y[v][p] = 0.0f;

    int a_mhalf = (lane >> 3) & 1, a_khalf = lane >> 4, a_row = lane & 7;
    int aoff = (mq * 16 + a_mhalf * 8 + a_row) * 36 + a_khalf * 4;
    int b_row = lane & 7, b_khalf = (lane >> 3) & 1;
    int boff = (nq * 8 + b_row) * 36 + b_khalf * 4;

    const float AX0[4] = {1.f, 1.f, 1.f, 0.f};
    const float AX1[4] = {0.f, 1.f, -1.f, -1.f};

    for (int pos = 0; pos < 16; pos++) {
        int buf = pos & 1;
        asm volatile("cp.async.wait_group 0;" ::: "memory");
        __syncthreads();
        if (pos < 15) issueU(pos + 1, buf ^ 1);
        float acc[4] = {0.f, 0.f, 0.f, 0.f};
        uint32_t uB = sbase + (WG_U + buf * 2304) * 4;
        uint32_t vB = sbase + (WG_V + pos * 576) * 4;
        #pragma unroll
        for (int q = 0; q < 4; q++) {
            uint32_t a0, a1, a2, a3, b0, b1;
            ldsm4(a0, a1, a2, a3, uB + (aoff + q * 8) * 4);
            ldsm2(b0, b1, vB + (boff + q * 8) * 4);
            mma_f16(acc, a0, a1, a2, a3, b0, b1);
        }
        int xi = pos >> 2, nu = pos & 3;
        float cx0 = AX0[xi], cx1 = AX1[xi], cy0 = AX0[nu], cy1 = AX1[nu];
        #pragma unroll
        for (int v = 0; v < 4; v++) {
            float m = acc[v];
            Y[v][0] = fmaf(cx0 * cy0, m, Y[v][0]);
            Y[v][1] = fmaf(cx0 * cy1, m, Y[v][1]);
            Y[v][2] = fmaf(cx1 * cy0, m, Y[v][2]);
            Y[v][3] = fmaf(cx1 * cy1, m, Y[v][3]);
        }
    }

    // ---- epilogue: Y -> smem fp32 [64 px][68], then coalesced out ----
    float* smf = reinterpret_cast<float*>(sm);
    __syncthreads();
    #pragma unroll
    for (int v = 0; v < 4; v++) {
        int co = mq * 16 + (lane >> 2) + 8 * (v >> 1);
        int tile = nq * 8 + (lane & 3) * 2 + (v & 1);
        float bv = bias[co];
        #pragma unroll
        for (int x = 0; x < 2; x++)
            #pragma unroll
            for (int y = 0; y < 2; y++)
                smf[(x * 32 + tile * 2 + y) * 68 + co] = Y[v][x * 2 + y] + bv;
    }
    __syncthreads();
    size_t obase = ((size_t)b * HW + g * 64) * 64;
    float4 gsum = make_float4(0.f, 0.f, 0.f, 0.f);
    for (int idx = t; idx < 1024; idx += 256) {  // 64 px * 16 chunks of 4 co
        int px = idx >> 4, ck = idx & 15;
        float4 v = *reinterpret_cast<const float4*>(smf + px * 68 + ck * 4);
        size_t go = obase + (size_t)px * 64 + ck * 4;
        if (res) {
            uint2 rr = *reinterpret_cast<const uint2*>(res + go);
            const __half2* r2p = reinterpret_cast<const __half2*>(&rr);
            float2 a0 = __half22float2(r2p[0]), a1 = __half22float2(r2p[1]);
            v.x += a0.x; v.y += a0.y; v.z += a1.x; v.w += a1.y;
        }
        v.x = fmaxf(v.x, 0.f); v.y = fmaxf(v.y, 0.f);
        v.z = fmaxf(v.z, 0.f); v.w = fmaxf(v.w, 0.f);
        if (gap) { gsum.x += v.x; gsum.y += v.y; gsum.z += v.z; gsum.w += v.w; }
        __half h[4];
        h[0] = __float2half(v.x); h[1] = __float2half(v.y);
        h[2] = __float2half(v.z); h[3] = __float2half(v.w);
        *reinterpret_cast<uint2*>(out + go) = *reinterpret_cast<uint2*>(h);
    }
    if (gap) {
        int ch = (t & 15) * 4;
        atomicAdd(&gap[b * 64 + ch],     gsum.x);
        atomicAdd(&gap[b * 64 + ch + 1], gsum.y);
        atomicAdd(&gap[b * 64 + ch + 2], gsum.z);
        atomicAdd(&gap[b * 64 + ch + 3], gsum.w);
    }
}

// ---------------- resnet FC + masked merge into d_out ----------------
__global__ void fc_merge(const float* __restrict__ gap, const float* __restrict__ rfc,
                         const float* __restrict__ rfb, const int* __restrict__ flag,
                         float* out) {
    __shared__ float sg[64];
    int b = blockIdx.x, t = threadIdx.x;
    sg[t] = gap[b * 64 + t] * (1.0f / 1024.0f);
    __syncthreads();
    if (t < 10) {
        float a = rfb[t];
        #pragma unroll
        for (int k = 0; k < 64; k++) a = fmaf(sg[k], rfc[k * 10 + t], a);
        if (flag[b]) out[(size_t)b * 10 + t] = a;
    }
}

// ---------------- launcher ----------------
extern "C" void kernel_launch(void* const* d_in, const int* in_sizes, int n_in,
                              void* d_out, int out_size) {
    const float* x    = (const float*)d_in[0];
    const float* thr  = (const float*)d_in[1];
    const int*   lab  = (const int*)d_in[2];
    const float* lw1  = (const float*)d_in[3];
    const float* lb1  = (const float*)d_in[4];
    const float* lw2  = (const float*)d_in[5];
    const float* lb2  = (const float*)d_in[6];
    const float* lfc1 = (const float*)d_in[7];
    const float* lfb1 = (const float*)d_in[8];
    const float* lfc2 = (const float*)d_in[9];
    const float* lfb2 = (const float*)d_in[10];
    const float* lfc3 = (const float*)d_in[11];
    const float* lfb3 = (const float*)d_in[12];
    const float* rw0  = (const float*)d_in[13];
    const float* rb0  = (const float*)d_in[14];
    const float* rw1a = (const float*)d_in[15];
    const float* rb1a = (const float*)d_in[16];
    const float* rw1b = (const float*)d_in[17];
    const float* rb1b = (const float*)d_in[18];
    const float* rw2a = (const float*)d_in[19];
    const float* rb2a = (const float*)d_in[20];
    const float* rw2b = (const float*)d_in[21];
    const float* rb2b = (const float*)d_in[22];
    const float* rfc  = (const float*)d_in[23];
    const float* rfb  = (const float*)d_in[24];

    float* out  = (float*)d_out;
    float* conf = out + BATCH * 10;

    __half *H, *R, *U, *W0;
    float *gapb; int* flag;
    cudaGetSymbolAddress((void**)&H,    g_H);
    cudaGetSymbolAddress((void**)&R,    g_R);
    cudaGetSymbolAddress((void**)&U,    g_U);
    cudaGetSymbolAddress((void**)&W0,   g_W0);
    cudaGetSymbolAddress((void**)&gapb, g_gap);
    cudaGetSymbolAddress((void**)&flag, g_flag);

    cudaFuncSetAttribute(conv_wino, cudaFuncAttributeMaxDynamicSharedMemorySize, WG_BYTES);
    cudaFuncSetAttribute(conv0_mma, cudaFuncAttributeMaxDynamicSharedMemorySize,
                         C0_SMEM_BYTES);

    dim3 gp(16, 4);
    prep_wu<<<gp, 256>>>(rw1a, rw1b, rw2a, rw2b, U);
    prep_w0<<<10, 256>>>(rw0, W0);
    zero_conf<<<1, 128>>>(conf);

    // LeNet branch (fp32 exact) + gap zero
    lenet_all<<<BATCH, 256>>>(x, lw1, lb1, lw2, lb2, lfc1, lfb1, lfc2, lfb2,
                              lfc3, lfb3, thr, lab, out, conf, flag, gapb);

    // ResNet branch: conv0 GEMM, then 4 Winograd layers
    const int UL = 16 * 64 * 72;
    dim3 g0(BATCH, 4);
    conv0_mma<<<g0, 256, C0_SMEM_BYTES>>>(x, W0, rb0, H);
    dim3 g(BATCH, 16);
    conv_wino<<<g, 256, WG_BYTES>>>(H, U + 0 * UL, rb1a, nullptr, R, nullptr);
    conv_wino<<<g, 256, WG_BYTES>>>(R, U + 1 * UL, rb1b, H,       H, nullptr);
    conv_wino<<<g, 256, WG_BYTES>>>(H, U + 2 * UL, rb2a, nullptr, R, nullptr);
    conv_wino<<<g, 256, WG_BYTES>>>(R, U + 3 * UL, rb2b, H,       H, gapb);

    fc_merge<<<BATCH, 64>>>(gapb, rfc, rfb, flag, out);
}

// round 16
// speedup vs baseline: 1.9955x; 1.9955x over previous
#include <cuda_runtime.h>
#include <cuda_fp16.h>
#include <cstdint>
#include <cstddef>

#define BATCH 1024
#define HW 1024   // 32*32

// ---------------- scratch (device globals; no allocs allowed) ----------------
__device__ __half g_H[(size_t)BATCH * HW * 64];   // 128 MB, fp16 NHWC activations
__device__ __half g_R[(size_t)BATCH * HW * 64];
__device__ __half g_W[4 * 9 * 64 * 72];           // fp16 conv weights (single term)
__device__ __half g_W0[64 * 40];                  // conv0 im2col weights [co][pitch 40 halves]
__device__ float g_gap[BATCH * 64];
__device__ int   g_flag[BATCH];

// ---------------- misc ----------------
__global__ void zero_conf(float* conf) {
    int t = threadIdx.x;
    if (t < 100) conf[t] = 0.0f;
}

// weight prep: OIHW fp32 [64][64][3][3] -> [s=9][co=64][ci pad 72] fp16
__global__ void prep_w(const float* __restrict__ w, __half* __restrict__ wo) {
    int idx = blockIdx.x * 256 + threadIdx.x;          // 9*64*72 = 41472
    if (idx >= 9 * 64 * 72) return;
    int s = idx / (64 * 72), rem = idx % (64 * 72), co = rem / 72, ci = rem % 72;
    float v = 0.0f;
    if (ci < 64) v = w[(co * 64 + ci) * 9 + s];
    wo[idx] = __float2half(v);
}

// conv0 weight prep: [64][3][3][3] fp32 -> [co][k pad 40] fp16, k = ci*9+ky*3+kx
__global__ void prep_w0(const float* __restrict__ w, __half* __restrict__ wo) {
    int idx = blockIdx.x * 256 + threadIdx.x;          // 64*40 = 2560
    if (idx >= 64 * 40) return;
    int co = idx / 40, k = idx % 40;
    float v = (k < 27) ? w[co * 27 + k] : 0.0f;
    wo[idx] = __float2half(v);
}

// ---------------- fused LeNet (fp32 exact, register-blocked convs) ----------------
__global__ __launch_bounds__(256) void lenet_all(
        const float* __restrict__ x, const float* __restrict__ w1, const float* __restrict__ b1,
        const float* __restrict__ w2, const float* __restrict__ b2,
        const float* __restrict__ fc1w, const float* __restrict__ fc1b,
        const float* __restrict__ fc2w, const float* __restrict__ fc2b,
        const float* __restrict__ fc3w, const float* __restrict__ fc3b,
        const float* __restrict__ thr_p, const int* __restrict__ labels,
        float* __restrict__ lenout, float* conf, int* __restrict__ flag,
        float* __restrict__ gapz) {
    __shared__ float sx[3 * 32 * 32];
    __shared__ float sw[2400];
    __shared__ float p1[6 * 14 * 14];
    __shared__ float p2[400];
    __shared__ float h1[120];
    __shared__ float h2[84];
    __shared__ float lg[10];
    int bid = blockIdx.x, t = threadIdx.x;
    if (t < 64) gapz[bid * 64 + t] = 0.0f;
    const float* xb = x + (size_t)bid * 3072;
    for (int i = t; i < 3072; i += 256) sx[i] = xb[i];
    for (int i = t; i < 450; i += 256) sw[i] = w1[i];
    __syncthreads();

    // ---- conv1 (3->6, 5x5 VALID) + 2x2 maxpool, register-blocked ----
    // task: (c, py, xg) -> 2x4 conv patch = 1x2 pool outputs; 6*14*7 = 588 tasks
    for (int tau = t; tau < 588; tau += 256) {
        int c = tau / 98, r = tau - c * 98, py = r / 7, xg = r - py * 7;
        int y0 = 2 * py, x0 = 4 * xg * 2;     // conv rows y0..y0+1, cols 4xg*2? no:
        x0 = 4 * xg;                          // conv cols 4xg..4xg+3 (2 pool cols)
        float acc[2][4];
        float bv = b1[c];
        #pragma unroll
        for (int dy = 0; dy < 2; dy++)
            #pragma unroll
            for (int dx = 0; dx < 4; dx++) acc[dy][dx] = bv;
        for (int ci = 0; ci < 3; ci++) {
            float wr[5][5];
            const float* wp = sw + (c * 3 + ci) * 25;
            #pragma unroll
            for (int ky = 0; ky < 5; ky++)
                #pragma unroll
                for (int kx = 0; kx < 5; kx++) wr[ky][kx] = wp[ky * 5 + kx];
            const float* sxp = sx + ci * 1024;
            #pragma unroll
            for (int ry = 0; ry < 6; ry++) {
                float xr[8];
                const float* rp = sxp + (y0 + ry) * 32 + x0;
                #pragma unroll
                for (int k = 0; k < 8; k++) xr[k] = rp[k];
                #pragma unroll
                for (int dy = 0; dy < 2; dy++) {
                    int ky = ry - dy;
                    if (ky >= 0 && ky < 5) {
                        #pragma unroll
                        for (int dx = 0; dx < 4; dx++)
                            #pragma unroll
                            for (int kx = 0; kx < 5; kx++)
                                acc[dy][dx] = fmaf(xr[dx + kx], wr[ky][kx], acc[dy][dx]);
                    }
                }
            }
        }
        #pragma unroll
        for (int j = 0; j < 2; j++) {
            float m = fmaxf(fmaxf(acc[0][2 * j], acc[0][2 * j + 1]),
                            fmaxf(acc[1][2 * j], acc[1][2 * j + 1]));
            p1[c * 196 + py * 14 + 2 * xg + j] = fmaxf(m, 0.0f);
        }
    }
    __syncthreads();
    for (int i = t; i < 2400; i += 256) sw[i] = w2[i];
    __syncthreads();

    // ---- conv2 (6->16, 5x5 VALID) + 2x2 maxpool, register-blocked ----
    // task: (co, py, px) -> 2x2 conv patch = 1 pool output; 16*25 = 400 tasks
    for (int tau = t; tau < 400; tau += 256) {
        int co = tau / 25, r = tau - co * 25, py = r / 5, px = r - py * 5;
        int y0 = 2 * py, x0 = 2 * px;
        float acc[2][2];
        float bv = b2[co];
        acc[0][0] = bv; acc[0][1] = bv; acc[1][0] = bv; acc[1][1] = bv;
        for (int ci = 0; ci < 6; ci++) {
            float wr[5][5];
            const float* wp = sw + (co * 6 + ci) * 25;
            #pragma unroll
            for (int ky = 0; ky < 5; ky++)
                #pragma unroll
                for (int kx = 0; kx < 5; kx++) wr[ky][kx] = wp[ky * 5 + kx];
            const float* pp = p1 + ci * 196;
            float xin[6][6];
            #pragma unroll
            for (int ry = 0; ry < 6; ry++)
                #pragma unroll
                for (int cx = 0; cx < 6; cx++)
                    xin[ry][cx] = pp[(y0 + ry) * 14 + x0 + cx];
            #pragma unroll
            for (int dy = 0; dy < 2; dy++)
                #pragma unroll
                for (int dx = 0; dx < 2; dx++)
                    #pragma unroll
                    for (int ky = 0; ky < 5; ky++)
                        #pragma unroll
                        for (int kx = 0; kx < 5; kx++)
                            acc[dy][dx] = fmaf(xin[dy + ky][dx + kx], wr[ky][kx],
                                               acc[dy][dx]);
        }
        float m = fmaxf(fmaxf(acc[0][0], acc[0][1]), fmaxf(acc[1][0], acc[1][1]));
        p2[co * 25 + py * 5 + px] = fmaxf(m, 0.0f);
    }
    __syncthreads();
    if (t < 120) {
        float a = fc1b[t];
        for (int k = 0; k < 400; k++) a = fmaf(p2[k], fc1w[k * 120 + t], a);
        h1[t] = fmaxf(a, 0.0f);
    }
    __syncthreads();
    if (t < 84) {
        float a = fc2b[t];
        for (int k = 0; k < 120; k++) a = fmaf(h1[k], fc2w[k * 84 + t], a);
        h2[t] = fmaxf(a, 0.0f);
    }
    __syncthreads();
    if (t < 10) {
        float a = fc3b[t];
        for (int k = 0; k < 84; k++) a = fmaf(h2[k], fc3w[k * 10 + t], a);
        lg[t] = a;
        lenout[(size_t)bid * 10 + t] = a;
    }
    __syncthreads();
    if (t == 0) {
        float m = lg[0]; int am = 0;
        #pragma unroll
        for (int i = 1; i < 10; i++) if (lg[i] > m) { m = lg[i]; am = i; }
        float p[10]; float s = 0.0f;
        #pragma unroll
        for (int i = 0; i < 10; i++) { p[i] = expf(lg[i] - m); s += p[i]; }
        float inv = 1.0f / s;
        float p0 = -1.0f, pp1 = -1.0f;
        #pragma unroll
        for (int i = 0; i < 10; i++) {
            float v = p[i] * inv;
            if (v > p0) { pp1 = p0; p0 = v; } else if (v > pp1) { pp1 = v; }
        }
        flag[bid] = ((p0 - pp1) <= thr_p[0]) ? 1 : 0;
        atomicAdd(&conf[labels[bid] * 10 + am], 1.0f);
    }
}

// ---------------- mma/ldmatrix helpers ----------------
__device__ __forceinline__ void mma_f16(float* d, uint32_t a0, uint32_t a1, uint32_t a2,
                                        uint32_t a3, uint32_t b0, uint32_t b1) {
    asm volatile("mma.sync.aligned.m16n8k16.row.col.f32.f16.f16.f32 "
                 "{%0,%1,%2,%3}, {%4,%5,%6,%7}, {%8,%9}, {%0,%1,%2,%3};"
                 : "+f"(d[0]), "+f"(d[1]), "+f"(d[2]), "+f"(d[3])
                 : "r"(a0), "r"(a1), "r"(a2), "r"(a3), "r"(b0), "r"(b1));
}
__device__ __forceinline__ void ldsm4(uint32_t& r0, uint32_t& r1, uint32_t& r2, uint32_t& r3,
                                      uint32_t addr) {
    asm volatile("ldmatrix.sync.aligned.m8n8.x4.shared.b16 {%0,%1,%2,%3}, [%4];"
                 : "=r"(r0), "=r"(r1), "=r"(r2), "=r"(r3) : "r"(addr));
}

// ---------------- conv0 as im2col fp16 GEMM: M=64co, K=32, N=256px/CTA ----------------
#define C0_SIN 0
#define C0_A   1080
#define C0_B   2360
#define C0_SMEM_BYTES (256 * 68 * 4)   // 69632

__global__ __launch_bounds__(256, 2) void conv0_mma(const float* __restrict__ x,
        const __half* __restrict__ w0, const float* __restrict__ bias,
        __half* __restrict__ out) {
    extern __shared__ uint32_t sm[];
    uint32_t sbase = (uint32_t)__cvta_generic_to_shared(sm);
    float* sin = reinterpret_cast<float*>(sm + C0_SIN);
    int b = blockIdx.x, row0 = blockIdx.y * 8;
    int t = threadIdx.x, lane = t & 31, warp = t >> 5;
    int cobase = (warp >> 2) * 32;
    int pxbase = (warp & 3) * 64;

    const float* inb = x + (size_t)b * 3 * HW;
    for (int idx = t; idx < 3 * 340; idx += 256) {
        int kc = idx / 340, rem = idx % 340, r = rem / 34, c = rem % 34;
        int gr = row0 - 1 + r, gc = c - 1;
        float v = 0.0f;
        if ((unsigned)gr < 32u && (unsigned)gc < 32u)
            v = inb[(size_t)kc * HW + gr * 32 + gc];
        sin[kc * 360 + r * 36 + c] = v;
    }
    for (int i = t; i < 1280; i += 256)
        sm[C0_A + i] = reinterpret_cast<const uint32_t*>(w0)[i];
    __syncthreads();
    {
        int r = t >> 5, c = t & 31;
        __half hv[32];
        #pragma unroll
        for (int ci = 0; ci < 3; ci++)
            #pragma unroll
            for (int ky = 0; ky < 3; ky++)
                #pragma unroll
                for (int kx = 0; kx < 3; kx++)
                    hv[ci * 9 + ky * 3 + kx] =
                        __float2half(sin[ci * 360 + (r + ky) * 36 + (c + kx)]);
        #pragma unroll
        for (int k = 27; k < 32; k++) hv[k] = __float2half(0.0f);
        uint32_t* hw = reinterpret_cast<uint32_t*>(hv);
        #pragma unroll
        for (int wv = 0; wv < 16; wv++) sm[C0_B + t * 20 + wv] = hw[wv];
    }
    __syncthreads();

    float acc[2][8][4];
    #pragma unroll
    for (int mt = 0; mt < 2; mt++) {
        float bv0 = bias[cobase + mt * 16 + (lane >> 2)];
        float bv1 = bias[cobase + mt * 16 + (lane >> 2) + 8];
        #pragma unroll
        for (int j = 0; j < 8; j++) {
            acc[mt][j][0] = bv0; acc[mt][j][1] = bv0;
            acc[mt][j][2] = bv1; acc[mt][j][3] = bv1;
        }
    }
    int a_mhalf = (lane >> 3) & 1, a_khalf = lane >> 4, a_row = lane & 7;
    int b_pxg = lane >> 4, b_khalf = (lane >> 3) & 1, b_row = lane & 7;
    #pragma unroll
    for (int q = 0; q < 2; q++) {
        uint32_t ah[2][4];
        #pragma unroll
        for (int mt = 0; mt < 2; mt++) {
            int aoff = (cobase + mt * 16 + a_mhalf * 8 + a_row) * 20 + q * 8 + a_khalf * 4;
            ldsm4(ah[mt][0], ah[mt][1], ah[mt][2], ah[mt][3], sbase + (C0_A + aoff) * 4);
        }
        #pragma unroll
        for (int jp = 0; jp < 4; jp++) {
            uint32_t bh[4];
            int p = pxbase + jp * 16 + b_pxg * 8 + b_row;
            int boff = p * 20 + q * 8 + b_khalf * 4;
            ldsm4(bh[0], bh[1], bh[2], bh[3], sbase + (C0_B + boff) * 4);
            #pragma unroll
            for (int sub = 0; sub < 2; sub++) {
                int j = jp * 2 + sub, hf = sub * 2;
                #pragma unroll
                for (int mt = 0; mt < 2; mt++)
                    mma_f16(acc[mt][j], ah[mt][0], ah[mt][1], ah[mt][2], ah[mt][3],
                            bh[hf], bh[hf + 1]);
            }
        }
    }
    float* smf = reinterpret_cast<float*>(sm);
    __syncthreads();
    #pragma unroll
    for (int mt = 0; mt < 2; mt++) {
        int col = cobase + mt * 16 + (lane >> 2);
        #pragma unroll
        for (int j = 0; j < 8; j++) {
            int p0 = pxbase + j * 8 + (lane & 3) * 2;
            smf[p0 * 68 + col]            = acc[mt][j][0];
            smf[(p0 + 1) * 68 + col]      = acc[mt][j][1];
            smf[p0 * 68 + col + 8]        = acc[mt][j][2];
            smf[(p0 + 1) * 68 + col + 8]  = acc[mt][j][3];
        }
    }
    __syncthreads();
    size_t obase = ((size_t)b * HW + row0 * 32) * 64;
    for (int idx = t; idx < 4096; idx += 256) {
        int px = idx >> 4, ck = idx & 15;
        float4 v = *reinterpret_cast<const float4*>(smf + px * 68 + ck * 4);
        v.x = fmaxf(v.x, 0.f); v.y = fmaxf(v.y, 0.f);
        v.z = fmaxf(v.z, 0.f); v.w = fmaxf(v.w, 0.f);
        __half h[4];
        h[0] = __float2half(v.x); h[1] = __float2half(v.y);
        h[2] = __float2half(v.z); h[3] = __float2half(v.w);
        *reinterpret_cast<uint2*>(out + obase + (size_t)px * 64 + ck * 4) =
            *reinterpret_cast<uint2*>(h);
    }
}

// ---------------- fp16 1-term tensor-core 3x3 SAME conv, 64->64, NHWC ----------------
#define IN_PITCH 36
#define PLANE    7344
#define WOFF     7344
#define WPLANE   2304
#define SMEM_WORDS (WOFF + 2 * WPLANE)              // 11952
#define SMEM_BYTES (SMEM_WORDS * 4)                 // 47808

__global__ __launch_bounds__(256, 3) void conv_mma(
        const __half* __restrict__ in,
        const __half* __restrict__ w,
        const float* __restrict__ bias,
        const __half* res,
        __half* __restrict__ out,
        float* gap) {
    extern __shared__ uint32_t sm[];
    uint32_t sbase = (uint32_t)__cvta_generic_to_shared(sm);
    int b = blockIdx.x, g = blockIdx.y, r0 = g * 4;
    int t = threadIdx.x, lane = t & 31, warp = t >> 5;
    int cobase = (warp >> 2) * 32;
    int pxbase = (warp & 3) * 32;

    const __half* ibase = in + (size_t)b * HW * 64;
    for (int idx = t; idx < 1632; idx += 256) {
        int pxt = idx >> 3, ck = idx & 7;
        int rt = pxt / 34, ct = pxt % 34;
        int gr = r0 - 1 + rt, gc = ct - 1;
        int ok = ((unsigned)gr < 32u) && ((unsigned)gc < 32u);
        const char* src = reinterpret_cast<const char*>(
            ibase + (ok ? ((size_t)(gr * 32 + gc)) * 64 + ck * 8 : 0));
        uint32_t dst = (uint32_t)__cvta_generic_to_shared(sm + pxt * IN_PITCH + ck * 4);
        int sz = ok ? 16 : 0;
        asm volatile("cp.async.ca.shared.global [%0], [%1], 16, %2;"
                     :: "r"(dst), "l"(src), "r"(sz));
    }

    auto issueW = [&](int s, int buf) {
        for (int c = t; c < 576; c += 256) {
            const char* src = reinterpret_cast<const char*>(w) + (size_t)s * 9216 + c * 16;
            uint32_t dst = (uint32_t)__cvta_generic_to_shared(
                sm + WOFF + buf * WPLANE + c * 4);
            asm volatile("cp.async.ca.shared.global [%0], [%1], 16;" :: "r"(dst), "l"(src));
        }
        asm volatile("cp.async.commit_group;" ::: "memory");
    };
    issueW(0, 0);

    float acc[2][4][4];
    #pragma unroll
    for (int mt = 0; mt < 2; mt++) {
        float bv0 = bias[cobase + mt * 16 + (lane >> 2)];
        float bv1 = bias[cobase + mt * 16 + (lane >> 2) + 8];
        #pragma unroll
        for (int j = 0; j < 4; j++) {
            acc[mt][j][0] = bv0; acc[mt][j][1] = bv0;
            acc[mt][j][2] = bv1; acc[mt][j][3] = bv1;
        }
    }

    int a_mhalf = (lane >> 3) & 1, a_khalf = lane >> 4, a_row = lane & 7;
    int aoff[2];
    #pragma unroll
    for (int mt = 0; mt < 2; mt++)
        aoff[mt] = (cobase + mt * 16 + a_mhalf * 8 + a_row) * IN_PITCH + a_khalf * 4;
    int b_pxg = lane >> 4, b_khalf = (lane >> 3) & 1, b_row = lane & 7;
    int boff[2];
    #pragma unroll
    for (int jp = 0; jp < 2; jp++) {
        int p = pxbase + jp * 16 + b_pxg * 8 + b_row;
        int rr = p >> 5, cc = p & 31;
        boff[jp] = (rr * 34 + cc) * IN_PITCH + b_khalf * 4;
    }

    for (int s = 0; s < 9; s++) {
        int buf = s & 1;
        asm volatile("cp.async.wait_group 0;" ::: "memory");
        __syncthreads();
        if (s < 8) issueW(s + 1, buf ^ 1);
        int ky = s / 3, kx = s - 3 * ky;
        int soff = (ky * 34 + kx) * IN_PITCH;
        uint32_t whB = sbase + (WOFF + buf * WPLANE) * 4;
        uint32_t ihB = sbase + soff * 4;
        #pragma unroll
        for (int q = 0; q < 4; q++) {
            uint32_t ah[2][4], bh[2][4];
            #pragma unroll
            for (int mt = 0; mt < 2; mt++)
                ldsm4(ah[mt][0], ah[mt][1], ah[mt][2], ah[mt][3],
                      whB + (aoff[mt] + q * 8) * 4);
            #pragma unroll
            for (int jp = 0; jp < 2; jp++)
                ldsm4(bh[jp][0], bh[jp][1], bh[jp][2], bh[jp][3],
                      ihB + (boff[jp] + q * 8) * 4);
            #pragma unroll
            for (int mt = 0; mt < 2; mt++)
                #pragma unroll
                for (int j = 0; j < 4; j++) {
                    int jp = j >> 1, hf = (j & 1) * 2;
                    mma_f16(acc[mt][j], ah[mt][0], ah[mt][1], ah[mt][2], ah[mt][3],
                            bh[jp][hf], bh[jp][hf + 1]);
                }
        }
    }

    float* smf = reinterpret_cast<float*>(sm);
    __syncthreads();
    {
        #pragma unroll
        for (int mt = 0; mt < 2; mt++) {
            int col = cobase + mt * 16 + (lane >> 2);
            #pragma unroll
            for (int j = 0; j < 4; j++) {
                int p0 = pxbase + j * 8 + (lane & 3) * 2;
                smf[p0 * 68 + col]            = acc[mt][j][0];
                smf[(p0 + 1) * 68 + col]      = acc[mt][j][1];
                smf[p0 * 68 + col + 8]        = acc[mt][j][2];
                smf[(p0 + 1) * 68 + col + 8]  = acc[mt][j][3];
            }
        }
    }
    __syncthreads();
    size_t obase = ((size_t)b * HW + g * 128) * 64;
    float4 gsum = make_float4(0.f, 0.f, 0.f, 0.f);
    for (int idx = t; idx < 2048; idx += 256) {
        int px = idx >> 4, ck = idx & 15;
        float4 v = *reinterpret_cast<const float4*>(smf + px * 68 + ck * 4);
        size_t go = obase + (size_t)px * 64 + ck * 4;
        if (res) {
            uint2 rr = *reinterpret_cast<const uint2*>(res + go);
            const __half2* r2p = reinterpret_cast<const __half2*>(&rr);
            float2 a0 = __half22float2(r2p[0]), a1 = __half22float2(r2p[1]);
            v.x += a0.x; v.y += a0.y; v.z += a1.x; v.w += a1.y;
        }
        v.x = fmaxf(v.x, 0.f); v.y = fmaxf(v.y, 0.f);
        v.z = fmaxf(v.z, 0.f); v.w = fmaxf(v.w, 0.f);
        if (gap) { gsum.x += v.x; gsum.y += v.y; gsum.z += v.z; gsum.w += v.w; }
        __half h[4];
        h[0] = __float2half(v.x); h[1] = __float2half(v.y);
        h[2] = __float2half(v.z); h[3] = __float2half(v.w);
        *reinterpret_cast<uint2*>(out + go) = *reinterpret_cast<uint2*>(h);
    }
    if (gap) {
        int ch = (t & 15) * 4;
        atomicAdd(&gap[b * 64 + ch],     gsum.x);
        atomicAdd(&gap[b * 64 + ch + 1], gsum.y);
        atomicAdd(&gap[b * 64 + ch + 2], gsum.z);
        atomicAdd(&gap[b * 64 + ch + 3], gsum.w);
    }
}

// ---------------- resnet FC + masked merge into d_out ----------------
__global__ void fc_merge(const float* __restrict__ gap, const float* __restrict__ rfc,
                         const float* __restrict__ rfb, const int* __restrict__ flag,
                         float* out) {
    __shared__ float sg[64];
    int b = blockIdx.x, t = threadIdx.x;
    sg[t] = gap[b * 64 + t] * (1.0f / 1024.0f);
    __syncthreads();
    if (t < 10) {
        float a = rfb[t];
        #pragma unroll
        for (int k = 0; k < 64; k++) a = fmaf(sg[k], rfc[k * 10 + t], a);
        if (flag[b]) out[(size_t)b * 10 + t] = a;
    }
}

// ---------------- launcher ----------------
extern "C" void kernel_launch(void* const* d_in, const int* in_sizes, int n_in,
                              void* d_out, int out_size) {
    const float* x    = (const float*)d_in[0];
    const float* thr  = (const float*)d_in[1];
    const int*   lab  = (const int*)d_in[2];
    const float* lw1  = (const float*)d_in[3];
    const float* lb1  = (const float*)d_in[4];
    const float* lw2  = (const float*)d_in[5];
    const float* lb2  = (const float*)d_in[6];
    const float* lfc1 = (const float*)d_in[7];
    const float* lfb1 = (const float*)d_in[8];
    const float* lfc2 = (const float*)d_in[9];
    const float* lfb2 = (const float*)d_in[10];
    const float* lfc3 = (const float*)d_in[11];
    const float* lfb3 = (const float*)d_in[12];
    const float* rw0  = (const float*)d_in[13];
    const float* rb0  = (const float*)d_in[14];
    const float* rw1a = (const float*)d_in[15];
    const float* rb1a = (const float*)d_in[16];
    const float* rw1b = (const float*)d_in[17];
    const float* rb1b = (const float*)d_in[18];
    const float* rw2a = (const float*)d_in[19];
    const float* rb2a = (const float*)d_in[20];
    const float* rw2b = (const float*)d_in[21];
    const float* rb2b = (const float*)d_in[22];
    const float* rfc  = (const float*)d_in[23];
    const float* rfb  = (const float*)d_in[24];

    float* out  = (float*)d_out;
    float* conf = out + BATCH * 10;

    __half *H, *R, *W, *W0;
    float *gapb; int* flag;
    cudaGetSymbolAddress((void**)&H,    g_H);
    cudaGetSymbolAddress((void**)&R,    g_R);
    cudaGetSymbolAddress((void**)&W,    g_W);
    cudaGetSymbolAddress((void**)&W0,   g_W0);
    cudaGetSymbolAddress((void**)&gapb, g_gap);
    cudaGetSymbolAddress((void**)&flag, g_flag);

    cudaFuncSetAttribute(conv_mma, cudaFuncAttributeMaxDynamicSharedMemorySize, SMEM_BYTES);
    cudaFuncSetAttribute(conv0_mma, cudaFuncAttributeMaxDynamicSharedMemorySize,
                         C0_SMEM_BYTES);

    const int WL = 9 * 64 * 72;
    prep_w<<<(WL + 255) / 256, 256>>>(rw1a, W + 0 * WL);
    prep_w<<<(WL + 255) / 256, 256>>>(rw1b, W + 1 * WL);
    prep_w<<<(WL + 255) / 256, 256>>>(rw2a, W + 2 * WL);
    prep_w<<<(WL + 255) / 256, 256>>>(rw2b, W + 3 * WL);
    prep_w0<<<10, 256>>>(rw0, W0);

    zero_conf<<<1, 128>>>(conf);

    // LeNet branch (fp32 exact, register-blocked) + gap zero
    lenet_all<<<BATCH, 256>>>(x, lw1, lb1, lw2, lb2, lfc1, lfb1, lfc2, lfb2,
                              lfc3, lfb3, thr, lab, out, conf, flag, gapb);

    // ResNet branch (fp16 NHWC activations, tensor cores end-to-end)
    dim3 g0(BATCH, 4);
    conv0_mma<<<g0, 256, C0_SMEM_BYTES>>>(x, W0, rb0, H);
    dim3 g(BATCH, 8);
    conv_mma<<<g, 256, SMEM_BYTES>>>(H, W + 0 * WL, rb1a, nullptr, R, nullptr);
    conv_mma<<<g, 256, SMEM_BYTES>>>(R, W + 1 * WL, rb1b, H,       H, nullptr);
    conv_mma<<<g, 256, SMEM_BYTES>>>(H, W + 2 * WL, rb2a, nullptr, R, nullptr);
    conv_mma<<<g, 256, SMEM_BYTES>>>(R, W + 3 * WL, rb2b, H,       H, gapb);

    fc_merge<<<BATCH, 64>>>(gapb, rfc, rfb, flag, out);
}

// round 17
// speedup vs baseline: 2.0258x; 1.0152x over previous
#include <cuda_runtime.h>
#include <cuda_fp16.h>
#include <cstdint>
#include <cstddef>

#define BATCH 1024
#define HW 1024   // 32*32

// ---------------- scratch (device globals; no allocs allowed) ----------------
__device__ __half g_H[(size_t)BATCH * HW * 64];   // 128 MB, fp16 NHWC activations
__device__ __half g_R[(size_t)BATCH * HW * 64];
__device__ __half g_W[4 * 9 * 64 * 72];           // fp16 conv weights
__device__ __half g_W0[64 * 40];                  // conv0 im2col weights
__device__ float g_gap[BATCH * 64];
__device__ int   g_flag[BATCH];

// ---------------- misc ----------------
__global__ void zero_conf(float* conf) {
    int t = threadIdx.x;
    if (t < 100) conf[t] = 0.0f;
}

// weight prep for all 4 layers: OIHW fp32 -> [s=9][co=64][ci pad 72] fp16
__global__ void prep_w4(const float* w1a, const float* w1b, const float* w2a,
                        const float* w2b, __half* __restrict__ wo) {
    int idx = blockIdx.x * 256 + threadIdx.x;          // 9*64*72 = 41472 per layer
    if (idx >= 9 * 64 * 72) return;
    int layer = blockIdx.y;
    const float* w = (layer == 0) ? w1a : (layer == 1) ? w1b : (layer == 2) ? w2a : w2b;
    int s = idx / (64 * 72), rem = idx % (64 * 72), co = rem / 72, ci = rem % 72;
    float v = 0.0f;
    if (ci < 64) v = w[(co * 64 + ci) * 9 + s];
    wo[(size_t)layer * 9 * 64 * 72 + idx] = __float2half(v);
}

// conv0 weight prep: [64][3][3][3] fp32 -> [co][k pad 40] fp16
__global__ void prep_w0(const float* __restrict__ w, __half* __restrict__ wo) {
    int idx = blockIdx.x * 256 + threadIdx.x;
    if (idx >= 64 * 40) return;
    int co = idx / 40, k = idx % 40;
    float v = (k < 27) ? w[co * 27 + k] : 0.0f;
    wo[idx] = __float2half(v);
}

// ---------------- fused LeNet (fp32 exact, register-blocked convs) ----------------
__global__ __launch_bounds__(256) void lenet_all(
        const float* __restrict__ x, const float* __restrict__ w1, const float* __restrict__ b1,
        const float* __restrict__ w2, const float* __restrict__ b2,
        const float* __restrict__ fc1w, const float* __restrict__ fc1b,
        const float* __restrict__ fc2w, const float* __restrict__ fc2b,
        const float* __restrict__ fc3w, const float* __restrict__ fc3b,
        const float* __restrict__ thr_p, const int* __restrict__ labels,
        float* __restrict__ lenout, float* conf, int* __restrict__ flag) {
    __shared__ float sx[3 * 32 * 32];
    __shared__ float sw[2400];
    __shared__ float p1[6 * 14 * 14];
    __shared__ float p2[400];
    __shared__ float h1[120];
    __shared__ float h2[84];
    __shared__ float lg[10];
    int bid = blockIdx.x, t = threadIdx.x;
    const float* xb = x + (size_t)bid * 3072;
    for (int i = t; i < 3072; i += 256) sx[i] = xb[i];
    for (int i = t; i < 450; i += 256) sw[i] = w1[i];
    __syncthreads();

    // conv1 (3->6, 5x5 VALID) + pool, register-blocked
    for (int tau = t; tau < 588; tau += 256) {
        int c = tau / 98, r = tau - c * 98, py = r / 7, xg = r - py * 7;
        int y0 = 2 * py, x0 = 4 * xg;
        float acc[2][4];
        float bv = b1[c];
        #pragma unroll
        for (int dy = 0; dy < 2; dy++)
            #pragma unroll
            for (int dx = 0; dx < 4; dx++) acc[dy][dx] = bv;
        for (int ci = 0; ci < 3; ci++) {
            float wr[5][5];
            const float* wp = sw + (c * 3 + ci) * 25;
            #pragma unroll
            for (int ky = 0; ky < 5; ky++)
                #pragma unroll
                for (int kx = 0; kx < 5; kx++) wr[ky][kx] = wp[ky * 5 + kx];
            const float* sxp = sx + ci * 1024;
            #pragma unroll
            for (int ry = 0; ry < 6; ry++) {
                float xr[8];
                const float* rp = sxp + (y0 + ry) * 32 + x0;
                #pragma unroll
                for (int k = 0; k < 8; k++) xr[k] = rp[k];
                #pragma unroll
                for (int dy = 0; dy < 2; dy++) {
                    int ky = ry - dy;
                    if (ky >= 0 && ky < 5) {
                        #pragma unroll
                        for (int dx = 0; dx < 4; dx++)
                            #pragma unroll
                            for (int kx = 0; kx < 5; kx++)
                                acc[dy][dx] = fmaf(xr[dx + kx], wr[ky][kx], acc[dy][dx]);
                    }
                }
            }
        }
        #pragma unroll
        for (int j = 0; j < 2; j++) {
            float m = fmaxf(fmaxf(acc[0][2 * j], acc[0][2 * j + 1]),
                            fmaxf(acc[1][2 * j], acc[1][2 * j + 1]));
            p1[c * 196 + py * 14 + 2 * xg + j] = fmaxf(m, 0.0f);
        }
    }
    __syncthreads();
    for (int i = t; i < 2400; i += 256) sw[i] = w2[i];
    __syncthreads();

    // conv2 (6->16, 5x5 VALID) + pool, register-blocked
    for (int tau = t; tau < 400; tau += 256) {
        int co = tau / 25, r = tau - co * 25, py = r / 5, px = r - py * 5;
        int y0 = 2 * py, x0 = 2 * px;
        float acc[2][2];
        float bv = b2[co];
        acc[0][0] = bv; acc[0][1] = bv; acc[1][0] = bv; acc[1][1] = bv;
        for (int ci = 0; ci < 6; ci++) {
            float wr[5][5];
            const float* wp = sw + (co * 6 + ci) * 25;
            #pragma unroll
            for (int ky = 0; ky < 5; ky++)
                #pragma unroll
                for (int kx = 0; kx < 5; kx++) wr[ky][kx] = wp[ky * 5 + kx];
            const float* pp = p1 + ci * 196;
            float xin[6][6];
            #pragma unroll
            for (int ry = 0; ry < 6; ry++)
                #pragma unroll
                for (int cx = 0; cx < 6; cx++)
                    xin[ry][cx] = pp[(y0 + ry) * 14 + x0 + cx];
            #pragma unroll
            for (int dy = 0; dy < 2; dy++)
                #pragma unroll
                for (int dx = 0; dx < 2; dx++)
                    #pragma unroll
                    for (int ky = 0; ky < 5; ky++)
                        #pragma unroll
                        for (int kx = 0; kx < 5; kx++)
                            acc[dy][dx] = fmaf(xin[dy + ky][dx + kx], wr[ky][kx],
                                               acc[dy][dx]);
        }
        float m = fmaxf(fmaxf(acc[0][0], acc[0][1]), fmaxf(acc[1][0], acc[1][1]));
        p2[co * 25 + py * 5 + px] = fmaxf(m, 0.0f);
    }
    __syncthreads();
    if (t < 120) {
        float a = fc1b[t];
        for (int k = 0; k < 400; k++) a = fmaf(p2[k], fc1w[k * 120 + t], a);
        h1[t] = fmaxf(a, 0.0f);
    }
    __syncthreads();
    if (t < 84) {
        float a = fc2b[t];
        for (int k = 0; k < 120; k++) a = fmaf(h1[k], fc2w[k * 84 + t], a);
        h2[t] = fmaxf(a, 0.0f);
    }
    __syncthreads();
    if (t < 10) {
        float a = fc3b[t];
        for (int k = 0; k < 84; k++) a = fmaf(h2[k], fc3w[k * 10 + t], a);
        lg[t] = a;
        lenout[(size_t)bid * 10 + t] = a;
    }
    __syncthreads();
    if (t == 0) {
        float m = lg[0]; int am = 0;
        #pragma unroll
        for (int i = 1; i < 10; i++) if (lg[i] > m) { m = lg[i]; am = i; }
        float p[10]; float s = 0.0f;
        #pragma unroll
        for (int i = 0; i < 10; i++) { p[i] = expf(lg[i] - m); s += p[i]; }
        float inv = 1.0f / s;
        float p0 = -1.0f, pp1 = -1.0f;
        #pragma unroll
        for (int i = 0; i < 10; i++) {
            float v = p[i] * inv;
            if (v > p0) { pp1 = p0; p0 = v; } else if (v > pp1) { pp1 = v; }
        }
        flag[bid] = ((p0 - pp1) <= thr_p[0]) ? 1 : 0;
        atomicAdd(&conf[labels[bid] * 10 + am], 1.0f);
    }
}

// ---------------- mma/ldmatrix helpers ----------------
__device__ __forceinline__ void mma_f16(float* d, uint32_t a0, uint32_t a1, uint32_t a2,
                                        uint32_t a3, uint32_t b0, uint32_t b1) {
    asm volatile("mma.sync.aligned.m16n8k16.row.col.f32.f16.f16.f32 "
                 "{%0,%1,%2,%3}, {%4,%5,%6,%7}, {%8,%9}, {%0,%1,%2,%3};"
                 : "+f"(d[0]), "+f"(d[1]), "+f"(d[2]), "+f"(d[3])
                 : "r"(a0), "r"(a1), "r"(a2), "r"(a3), "r"(b0), "r"(b1));
}
__device__ __forceinline__ void ldsm4(uint32_t& r0, uint32_t& r1, uint32_t& r2, uint32_t& r3,
                                      uint32_t addr) {
    asm volatile("ldmatrix.sync.aligned.m8n8.x4.shared.b16 {%0,%1,%2,%3}, [%4];"
                 : "=r"(r0), "=r"(r1), "=r"(r2), "=r"(r3) : "r"(addr));
}

// ---------------- conv0 as im2col fp16 GEMM (also zeroes gap) ----------------
#define C0_SIN 0
#define C0_A   1080
#define C0_B   2360
#define C0_SMEM_BYTES (256 * 68 * 4)   // 69632

__global__ __launch_bounds__(256, 2) void conv0_mma(const float* __restrict__ x,
        const __half* __restrict__ w0, const float* __restrict__ bias,
        __half* __restrict__ out, float* __restrict__ gapz) {
    extern __shared__ uint32_t sm[];
    uint32_t sbase = (uint32_t)__cvta_generic_to_shared(sm);
    float* sin = reinterpret_cast<float*>(sm + C0_SIN);
    int b = blockIdx.x, row0 = blockIdx.y * 8;
    int t = threadIdx.x, lane = t & 31, warp = t >> 5;
    int cobase = (warp >> 2) * 32;
    int pxbase = (warp & 3) * 64;

    if (blockIdx.y == 0 && t < 64) gapz[b * 64 + t] = 0.0f;   // gap zero (main stream)

    const float* inb = x + (size_t)b * 3 * HW;
    for (int idx = t; idx < 3 * 340; idx += 256) {
        int kc = idx / 340, rem = idx % 340, r = rem / 34, c = rem % 34;
        int gr = row0 - 1 + r, gc = c - 1;
        float v = 0.0f;
        if ((unsigned)gr < 32u && (unsigned)gc < 32u)
            v = inb[(size_t)kc * HW + gr * 32 + gc];
        sin[kc * 360 + r * 36 + c] = v;
    }
    for (int i = t; i < 1280; i += 256)
        sm[C0_A + i] = reinterpret_cast<const uint32_t*>(w0)[i];
    __syncthreads();
    {
        int r = t >> 5, c = t & 31;
        __half hv[32];
        #pragma unroll
        for (int ci = 0; ci < 3; ci++)
            #pragma unroll
            for (int ky = 0; ky < 3; ky++)
                #pragma unroll
                for (int kx = 0; kx < 3; kx++)
                    hv[ci * 9 + ky * 3 + kx] =
                        __float2half(sin[ci * 360 + (r + ky) * 36 + (c + kx)]);
        #pragma unroll
        for (int k = 27; k < 32; k++) hv[k] = __float2half(0.0f);
        uint32_t* hw = reinterpret_cast<uint32_t*>(hv);
        #pragma unroll
        for (int wv = 0; wv < 16; wv++) sm[C0_B + t * 20 + wv] = hw[wv];
    }
    __syncthreads();

    float acc[2][8][4];
    #pragma unroll
    for (int mt = 0; mt < 2; mt++) {
        float bv0 = bias[cobase + mt * 16 + (lane >> 2)];
        float bv1 = bias[cobase + mt * 16 + (lane >> 2) + 8];
        #pragma unroll
        for (int j = 0; j < 8; j++) {
            acc[mt][j][0] = bv0; acc[mt][j][1] = bv0;
            acc[mt][j][2] = bv1; acc[mt][j][3] = bv1;
        }
    }
    int a_mhalf = (lane >> 3) & 1, a_khalf = lane >> 4, a_row = lane & 7;
    int b_pxg = lane >> 4, b_khalf = (lane >> 3) & 1, b_row = lane & 7;
    #pragma unroll
    for (int q = 0; q < 2; q++) {
        uint32_t ah[2][4];
        #pragma unroll
        for (int mt = 0; mt < 2; mt++) {
            int aoff = (cobase + mt * 16 + a_mhalf * 8 + a_row) * 20 + q * 8 + a_khalf * 4;
            ldsm4(ah[mt][0], ah[mt][1], ah[mt][2], ah[mt][3], sbase + (C0_A + aoff) * 4);
        }
        #pragma unroll
        for (int jp = 0; jp < 4; jp++) {
            uint32_t bh[4];
            int p = pxbase + jp * 16 + b_pxg * 8 + b_row;
            int boff = p * 20 + q * 8 + b_khalf * 4;
            ldsm4(bh[0], bh[1], bh[2], bh[3], sbase + (C0_B + boff) * 4);
            #pragma unroll
            for (int sub = 0; sub < 2; sub++) {
                int j = jp * 2 + sub, hf = sub * 2;
                #pragma unroll
                for (int mt = 0; mt < 2; mt++)
                    mma_f16(acc[mt][j], ah[mt][0], ah[mt][1], ah[mt][2], ah[mt][3],
                            bh[hf], bh[hf + 1]);
            }
        }
    }
    float* smf = reinterpret_cast<float*>(sm);
    __syncthreads();
    #pragma unroll
    for (int mt = 0; mt < 2; mt++) {
        int col = cobase + mt * 16 + (lane >> 2);
        #pragma unroll
        for (int j = 0; j < 8; j++) {
            int p0 = pxbase + j * 8 + (lane & 3) * 2;
            smf[p0 * 68 + col]            = acc[mt][j][0];
            smf[(p0 + 1) * 68 + col]      = acc[mt][j][1];
            smf[p0 * 68 + col + 8]        = acc[mt][j][2];
            smf[(p0 + 1) * 68 + col + 8]  = acc[mt][j][3];
        }
    }
    __syncthreads();
    size_t obase = ((size_t)b * HW + row0 * 32) * 64;
    for (int idx = t; idx < 4096; idx += 256) {
        int px = idx >> 4, ck = idx & 15;
        float4 v = *reinterpret_cast<const float4*>(smf + px * 68 + ck * 4);
        v.x = fmaxf(v.x, 0.f); v.y = fmaxf(v.y, 0.f);
        v.z = fmaxf(v.z, 0.f); v.w = fmaxf(v.w, 0.f);
        __half h[4];
        h[0] = __float2half(v.x); h[1] = __float2half(v.y);
        h[2] = __float2half(v.z); h[3] = __float2half(v.w);
        *reinterpret_cast<uint2*>(out + obase + (size_t)px * 64 + ck * 4) =
            *reinterpret_cast<uint2*>(h);
    }
}

// ---------------- fp16 tensor-core 3x3 SAME conv, 64->64, NHWC ----------------
#define IN_PITCH 36
#define PLANE    7344
#define WOFF     7344
#define WPLANE   2304
#define SMEM_WORDS (WOFF + 2 * WPLANE)
#define SMEM_BYTES (SMEM_WORDS * 4)                 // 47808

__global__ __launch_bounds__(256, 3) void conv_mma(
        const __half* __restrict__ in,
        const __half* __restrict__ w,
        const float* __restrict__ bias,
        const __half* res,
        __half* __restrict__ out,
        float* gap) {
    extern __shared__ uint32_t sm[];
    uint32_t sbase = (uint32_t)__cvta_generic_to_shared(sm);
    int b = blockIdx.x, g = blockIdx.y, r0 = g * 4;
    int t = threadIdx.x, lane = t & 31, warp = t >> 5;
    int cobase = (warp >> 2) * 32;
    int pxbase = (warp & 3) * 32;

    const __half* ibase = in + (size_t)b * HW * 64;
    for (int idx = t; idx < 1632; idx += 256) {
        int pxt = idx >> 3, ck = idx & 7;
        int rt = pxt / 34, ct = pxt % 34;
        int gr = r0 - 1 + rt, gc = ct - 1;
        int ok = ((unsigned)gr < 32u) && ((unsigned)gc < 32u);
        const char* src = reinterpret_cast<const char*>(
            ibase + (ok ? ((size_t)(gr * 32 + gc)) * 64 + ck * 8 : 0));
        uint32_t dst = (uint32_t)__cvta_generic_to_shared(sm + pxt * IN_PITCH + ck * 4);
        int sz = ok ? 16 : 0;
        asm volatile("cp.async.ca.shared.global [%0], [%1], 16, %2;"
                     :: "r"(dst), "l"(src), "r"(sz));
    }

    auto issueW = [&](int s, int buf) {
        for (int c = t; c < 576; c += 256) {
            const char* src = reinterpret_cast<const char*>(w) + (size_t)s * 9216 + c * 16;
            uint32_t dst = (uint32_t)__cvta_generic_to_shared(
                sm + WOFF + buf * WPLANE + c * 4);
            asm volatile("cp.async.ca.shared.global [%0], [%1], 16;" :: "r"(dst), "l"(src));
        }
        asm volatile("cp.async.commit_group;" ::: "memory");
    };
    issueW(0, 0);

    float acc[2][4][4];
    #pragma unroll
    for (int mt = 0; mt < 2; mt++) {
        float bv0 = bias[cobase + mt * 16 + (lane >> 2)];
        float bv1 = bias[cobase + mt * 16 + (lane >> 2) + 8];
        #pragma unroll
        for (int j = 0; j < 4; j++) {
            acc[mt][j][0] = bv0; acc[mt][j][1] = bv0;
            acc[mt][j][2] = bv1; acc[mt][j][3] = bv1;
        }
    }

    int a_mhalf = (lane >> 3) & 1, a_khalf = lane >> 4, a_row = lane & 7;
    int aoff[2];
    #pragma unroll
    for (int mt = 0; mt < 2; mt++)
        aoff[mt] = (cobase + mt * 16 + a_mhalf * 8 + a_row) * IN_PITCH + a_khalf * 4;
    int b_pxg = lane >> 4, b_khalf = (lane >> 3) & 1, b_row = lane & 7;
    int boff[2];
    #pragma unroll
    for (int jp = 0; jp < 2; jp++) {
        int p = pxbase + jp * 16 + b_pxg * 8 + b_row;
        int rr = p >> 5, cc = p & 31;
        boff[jp] = (rr * 34 + cc) * IN_PITCH + b_khalf * 4;
    }

    for (int s = 0; s < 9; s++) {
        int buf = s & 1;
        asm volatile("cp.async.wait_group 0;" ::: "memory");
        __syncthreads();
        if (s < 8) issueW(s + 1, buf ^ 1);
        int ky = s / 3, kx = s - 3 * ky;
        int soff = (ky * 34 + kx) * IN_PITCH;
        uint32_t whB = sbase + (WOFF + buf * WPLANE) * 4;
        uint32_t ihB = sbase + soff * 4;
        #pragma unroll
        for (int q = 0; q < 4; q++) {
            uint32_t ah[2][4], bh[2][4];
            #pragma unroll
            for (int mt = 0; mt < 2; mt++)
                ldsm4(ah[mt][0], ah[mt][1], ah[mt][2], ah[mt][3],
                      whB + (aoff[mt] + q * 8) * 4);
            #pragma unroll
            for (int jp = 0; jp < 2; jp++)
                ldsm4(bh[jp][0], bh[jp][1], bh[jp][2], bh[jp][3],
                      ihB + (boff[jp] + q * 8) * 4);
            #pragma unroll
            for (int mt = 0; mt < 2; mt++)
                #pragma unroll
                for (int j = 0; j < 4; j++) {
                    int jp = j >> 1, hf = (j & 1) * 2;
                    mma_f16(acc[mt][j], ah[mt][0], ah[mt][1], ah[mt][2], ah[mt][3],
                            bh[jp][hf], bh[jp][hf + 1]);
                }
        }
    }

    float* smf = reinterpret_cast<float*>(sm);
    __syncthreads();
    {
        #pragma unroll
        for (int mt = 0; mt < 2; mt++) {
            int col = cobase + mt * 16 + (lane >> 2);
            #pragma unroll
            for (int j = 0; j < 4; j++) {
                int p0 = pxbase + j * 8 + (lane & 3) * 2;
                smf[p0 * 68 + col]            = acc[mt][j][0];
                smf[(p0 + 1) * 68 + col]      = acc[mt][j][1];
                smf[p0 * 68 + col + 8]        = acc[mt][j][2];
                smf[(p0 + 1) * 68 + col + 8]  = acc[mt][j][3];
            }
        }
    }
    __syncthreads();
    size_t obase = ((size_t)b * HW + g * 128) * 64;
    float4 gsum = make_float4(0.f, 0.f, 0.f, 0.f);
    for (int idx = t; idx < 2048; idx += 256) {
        int px = idx >> 4, ck = idx & 15;
        float4 v = *reinterpret_cast<const float4*>(smf + px * 68 + ck * 4);
        size_t go = obase + (size_t)px * 64 + ck * 4;
        if (res) {
            uint2 rr = *reinterpret_cast<const uint2*>(res + go);
            const __half2* r2p = reinterpret_cast<const __half2*>(&rr);
            float2 a0 = __half22float2(r2p[0]), a1 = __half22float2(r2p[1]);
            v.x += a0.x; v.y += a0.y; v.z += a1.x; v.w += a1.y;
        }
        v.x = fmaxf(v.x, 0.f); v.y = fmaxf(v.y, 0.f);
        v.z = fmaxf(v.z, 0.f); v.w = fmaxf(v.w, 0.f);
        if (gap) { gsum.x += v.x; gsum.y += v.y; gsum.z += v.z; gsum.w += v.w; }
        __half h[4];
        h[0] = __float2half(v.x); h[1] = __float2half(v.y);
        h[2] = __float2half(v.z); h[3] = __float2half(v.w);
        *reinterpret_cast<uint2*>(out + go) = *reinterpret_cast<uint2*>(h);
    }
    if (gap) {
        int ch = (t & 15) * 4;
        atomicAdd(&gap[b * 64 + ch],     gsum.x);
        atomicAdd(&gap[b * 64 + ch + 1], gsum.y);
        atomicAdd(&gap[b * 64 + ch + 2], gsum.z);
        atomicAdd(&gap[b * 64 + ch + 3], gsum.w);
    }
}

// ---------------- resnet FC + masked merge into d_out ----------------
__global__ void fc_merge(const float* __restrict__ gap, const float* __restrict__ rfc,
                         const float* __restrict__ rfb, const int* __restrict__ flag,
                         float* out) {
    __shared__ float sg[64];
    int b = blockIdx.x, t = threadIdx.x;
    sg[t] = gap[b * 64 + t] * (1.0f / 1024.0f);
    __syncthreads();
    if (t < 10) {
        float a = rfb[t];
        #pragma unroll
        for (int k = 0; k < 64; k++) a = fmaf(sg[k], rfc[k * 10 + t], a);
        if (flag[b]) out[(size_t)b * 10 + t] = a;
    }
}

// ---------------- launcher: fork-join graph (lenet overlaps conv chain) ----------------
extern "C" void kernel_launch(void* const* d_in, const int* in_sizes, int n_in,
                              void* d_out, int out_size) {
    const float* x    = (const float*)d_in[0];
    const float* thr  = (const float*)d_in[1];
    const int*   lab  = (const int*)d_in[2];
    const float* lw1  = (const float*)d_in[3];
    const float* lb1  = (const float*)d_in[4];
    const float* lw2  = (const float*)d_in[5];
    const float* lb2  = (const float*)d_in[6];
    const float* lfc1 = (const float*)d_in[7];
    const float* lfb1 = (const float*)d_in[8];
    const float* lfc2 = (const float*)d_in[9];
    const float* lfb2 = (const float*)d_in[10];
    const float* lfc3 = (const float*)d_in[11];
    const float* lfb3 = (const float*)d_in[12];
    const float* rw0  = (const float*)d_in[13];
    const float* rb0  = (const float*)d_in[14];
    const float* rw1a = (const float*)d_in[15];
    const float* rb1a = (const float*)d_in[16];
    const float* rw1b = (const float*)d_in[17];
    const float* rb1b = (const float*)d_in[18];
    const float* rw2a = (const float*)d_in[19];
    const float* rb2a = (const float*)d_in[20];
    const float* rw2b = (const float*)d_in[21];
    const float* rb2b = (const float*)d_in[22];
    const float* rfc  = (const float*)d_in[23];
    const float* rfb  = (const float*)d_in[24];

    float* out  = (float*)d_out;
    float* conf = out + BATCH * 10;

    __half *H, *R, *W, *W0;
    float *gapb; int* flag;
    cudaGetSymbolAddress((void**)&H,    g_H);
    cudaGetSymbolAddress((void**)&R,    g_R);
    cudaGetSymbolAddress((void**)&W,    g_W);
    cudaGetSymbolAddress((void**)&W0,   g_W0);
    cudaGetSymbolAddress((void**)&gapb, g_gap);
    cudaGetSymbolAddress((void**)&flag, g_flag);

    cudaFuncSetAttribute(conv_mma, cudaFuncAttributeMaxDynamicSharedMemorySize, SMEM_BYTES);
    cudaFuncSetAttribute(conv0_mma, cudaFuncAttributeMaxDynamicSharedMemorySize,
                         C0_SMEM_BYTES);

    // fork-join: side stream runs LeNet branch concurrently with conv chain
    cudaStream_t s2;
    cudaStreamCreateWithFlags(&s2, cudaStreamNonBlocking);
    cudaEvent_t eFork, eJoin;
    cudaEventCreateWithFlags(&eFork, cudaEventDisableTiming);
    cudaEventCreateWithFlags(&eJoin, cudaEventDisableTiming);

    cudaEventRecord(eFork, 0);
    cudaStreamWaitEvent(s2, eFork, 0);

    // ---- side stream: conf zero + LeNet (writes out logits, conf, flag) ----
    zero_conf<<<1, 128, 0, s2>>>(conf);
    lenet_all<<<BATCH, 256, 0, s2>>>(x, lw1, lb1, lw2, lb2, lfc1, lfb1, lfc2, lfb2,
                                     lfc3, lfb3, thr, lab, out, conf, flag);
    cudaEventRecord(eJoin, s2);

    // ---- main stream: weight preps + ResNet chain ----
    dim3 gpw((9 * 64 * 72 + 255) / 256, 4);
    prep_w4<<<gpw, 256>>>(rw1a, rw1b, rw2a, rw2b, W);
    prep_w0<<<10, 256>>>(rw0, W0);

    const int WL = 9 * 64 * 72;
    dim3 g0(BATCH, 4);
    conv0_mma<<<g0, 256, C0_SMEM_BYTES>>>(x, W0, rb0, H, gapb);   // also zeroes gap
    dim3 g(BATCH, 8);
    conv_mma<<<g, 256, SMEM_BYTES>>>(H, W + 0 * WL, rb1a, nullptr, R, nullptr);
    conv_mma<<<g, 256, SMEM_BYTES>>>(R, W + 1 * WL, rb1b, H,       H, nullptr);
    conv_mma<<<g, 256, SMEM_BYTES>>>(H, W + 2 * WL, rb2a, nullptr, R, nullptr);
    conv_mma<<<g, 256, SMEM_BYTES>>>(R, W + 3 * WL, rb2b, H,       H, gapb);

    // ---- join: fc_merge needs flag (side) + gap (main) ----
    cudaStreamWaitEvent(0, eJoin, 0);
    fc_merge<<<BATCH, 64>>>(gapb, rfc, rfb, flag, out);
}